// round 9
// baseline (speedup 1.0000x reference)
#include <cuda_runtime.h>
#include <cuda_fp16.h>
#include <cstdint>

// out[m,o] = sum_d FWHT(x)[m,d] * W[o,d] / sqrt(D) + b[o]
// Hadamard symmetric => FWHT(x) @ W^T == x @ (FWHT_rows(W))^T.
// fp16 single-pass HMMA GEMM w/ fp32 acc.
// R9: 8 warps, 64x64 warp tiles (min LDSM/MMA), swizzle offsets hoisted out
// of the mainloop (issue-slot bound: tensor busy 67% in R7/R8 regardless of
// warp count -> cut non-MMA issues).

#define D_DIM 2048
#define M_ROWS 16384
#define KDIM 2048
#define NDIM 2048

#define BM 256
#define BN 128
#define BK 64
#define NCH (KDIM / BK)            // 32 k-chunks
#define STAGES 3
#define TILE_A_B (BM * 128)        // 32 KB
#define TILE_B_B (BN * 128)        // 16 KB
#define STAGE_B (TILE_A_B + TILE_B_B)   // 48 KB
#define SMEM_TOTAL (STAGES * STAGE_B)   // 144 KB

// ---- device-global scratch ----
__device__ __half g_W_h[(size_t)NDIM * KDIM];     // 8 MB
__device__ __half g_x_h[(size_t)M_ROWS * KDIM];   // 64 MB

// ====================== PTX helpers ======================
__device__ __forceinline__ uint32_t smem_u32(const void* p) {
    uint32_t a;
    asm("{ .reg .u64 t; cvta.to.shared.u64 t, %1; cvt.u32.u64 %0, t; }" : "=r"(a) : "l"(p));
    return a;
}
#define CP16(dst, src) \
    asm volatile("cp.async.cg.shared.global [%0], [%1], 16;" :: "r"(dst), "l"(src))
#define CP_COMMIT() asm volatile("cp.async.commit_group;" ::: "memory")
#define CP_WAIT1()  asm volatile("cp.async.wait_group 1;" ::: "memory")

#define LDSM4(r0, r1, r2, r3, addr) \
    asm volatile("ldmatrix.sync.aligned.m8n8.x4.shared.b16 {%0,%1,%2,%3}, [%4];" \
                 : "=r"(r0), "=r"(r1), "=r"(r2), "=r"(r3) : "r"(addr))

__device__ __forceinline__ void mma16816(float* c, const uint32_t* a,
                                         uint32_t b0, uint32_t b1) {
    asm volatile(
        "mma.sync.aligned.m16n8k16.row.col.f32.f16.f16.f32 "
        "{%0,%1,%2,%3}, {%4,%5,%6,%7}, {%8,%9}, {%0,%1,%2,%3};"
        : "+f"(c[0]), "+f"(c[1]), "+f"(c[2]), "+f"(c[3])
        : "r"(a[0]), "r"(a[1]), "r"(a[2]), "r"(a[3]), "r"(b0), "r"(b1));
}

// ============ Kernel 1 (merged preprocessing) ============
// blocks [0, 2048):        FWHT row of W -> fp16 (scale folded)
// blocks [2048, 2048+16384): convert 2 float4-chunks of x -> fp16
__global__ __launch_bounds__(256) void preprocess(const float* __restrict__ W,
                                                  const float* __restrict__ x) {
    __shared__ float s[D_DIM];
    const int tid = threadIdx.x;
    if (blockIdx.x < D_DIM) {
        const float* row = W + (size_t)blockIdx.x * D_DIM;
        for (int i = tid; i < D_DIM; i += 256) s[i] = row[i];
        __syncthreads();
        #pragma unroll
        for (int lg = 0; lg < 11; lg++) {
            int h = 1 << lg;
            #pragma unroll
            for (int q = 0; q < (D_DIM / 2) / 256; q++) {
                int p = tid + q * 256;
                int i = ((p >> lg) << (lg + 1)) | (p & (h - 1));
                float a = s[i], c = s[i + h];
                s[i] = a + c;
                s[i + h] = a - c;
            }
            __syncthreads();
        }
        const float scale = 0.02209708691207961f;  // 1/sqrt(2048)
        size_t base = (size_t)blockIdx.x * D_DIM;
        for (int i = tid; i < D_DIM; i += 256)
            g_W_h[base + i] = __float2half_rn(s[i] * scale);
    } else {
        size_t b = (size_t)(blockIdx.x - D_DIM) * 512 + tid;   // float4 index
        #pragma unroll
        for (int u = 0; u < 2; u++) {
            size_t i = b + u * 256;
            float4 v = ((const float4*)x)[i];
            ((__half2*)g_x_h)[2 * i]     = __floats2half2_rn(v.x, v.y);
            ((__half2*)g_x_h)[2 * i + 1] = __floats2half2_rn(v.z, v.w);
        }
    }
}

// ====================== Kernel 2: fp16 HMMA GEMM + bias ======================
// 8 warps: wm = wid&3 (4 x 64 rows), wn = wid>>2 (2 x 64 cols). 64x64 warp tile.
// Per k16-step: 4 A-LDSM4 + 4 B-LDSM4, 32 MMAs. Offsets hoisted.

__global__ __launch_bounds__(256, 1)
void had_gemm_f16(const float* __restrict__ bias, float* __restrict__ C) {
    extern __shared__ __align__(1024) char smem[];
    const uint32_t sm0 = smem_u32(smem);

    const int tid  = threadIdx.x;
    const int lane = tid & 31;
    const int wid  = tid >> 5;
    const int wm   = wid & 3;
    const int wn   = wid >> 2;

    const int bm = blockIdx.y * BM;
    const int bn = blockIdx.x * BN;

    // ---- cp.async loader mapping ----
    const int lr = tid >> 3;
    const int lc = tid & 7;
    const uint32_t swchunk = (uint32_t)((lc ^ (lr & 7)) << 4);

    const __half* srcA = g_x_h + (size_t)(bm + lr) * KDIM + lc * 8;
    const __half* srcB = g_W_h + (size_t)(bn + lr) * KDIM + lc * 8;

    float acc[4][8][4];
    #pragma unroll
    for (int i = 0; i < 4; i++)
        #pragma unroll
        for (int j = 0; j < 8; j++)
            #pragma unroll
            for (int q = 0; q < 4; q++) acc[i][j][q] = 0.f;

    // ---- hoisted ldmatrix offsets ----
    // off(r, c, ks) = r*128 + ((2ks+c)^(r&7))<<4
    //              = [r*128 + ((c^(r&1))<<4)] + ((ks ^ ((r>>1)&3))<<5)
    const int raBase = wm * 64 + (lane & 15);                      // + tm*16
    const int cA     = lane >> 4;
    const int rbBase = wn * 64 + (lane & 7) + ((lane >> 4) << 3);  // + g*16
    const int cB     = (lane >> 3) & 1;

    const uint32_t qA = (uint32_t)((raBase >> 1) & 3);
    const uint32_t qB = (uint32_t)((rbBase >> 1) & 3);
    uint32_t baseA[4], baseB[4];
    #pragma unroll
    for (int tm = 0; tm < 4; tm++) {
        const int r = raBase + tm * 16;   // low 3 bits invariant in tm
        baseA[tm] = (uint32_t)r * 128 + (uint32_t)((cA ^ (r & 1)) << 4);
    }
    #pragma unroll
    for (int g = 0; g < 4; g++) {
        const int r = rbBase + g * 16;
        baseB[g] = (uint32_t)r * 128 + (uint32_t)((cB ^ (r & 1)) << 4) + TILE_A_B;
    }

    auto issue = [&](int s, int t) {
        const uint32_t sb = sm0 + s * STAGE_B;
        const size_t ko = (size_t)t * BK;
        #pragma unroll
        for (int i = 0; i < 8; i++) {                 // A: 256 rows
            uint32_t roff = (uint32_t)(lr + 32 * i) * 128 + swchunk;
            CP16(sb + roff, srcA + ko + (size_t)(32 * i) * KDIM);
        }
        #pragma unroll
        for (int i = 0; i < 4; i++) {                 // B: 128 rows
            uint32_t roff = (uint32_t)(lr + 32 * i) * 128 + swchunk;
            CP16(sb + TILE_A_B + roff, srcB + ko + (size_t)(32 * i) * KDIM);
        }
    };

    // distance-2 prefetch: iter-t writes stage (t+2)%3 != t%3 (read stage)
    issue(0, 0); CP_COMMIT();
    issue(1, 1); CP_COMMIT();

    for (int t = 0; t < NCH; t++) {
        CP_WAIT1();
        __syncthreads();

        if (t + 2 < NCH) issue((t + 2) % STAGES, t + 2);
        CP_COMMIT();

        const uint32_t stg = sm0 + (t % STAGES) * STAGE_B;

        #pragma unroll
        for (int ks = 0; ks < 4; ks++) {
            const uint32_t kqA = ((uint32_t)ks ^ qA) << 5;
            const uint32_t kqB = ((uint32_t)ks ^ qB) << 5;
            uint32_t ah[4][4], bh[4][4];
            #pragma unroll
            for (int tm = 0; tm < 4; tm++)
                LDSM4(ah[tm][0], ah[tm][1], ah[tm][2], ah[tm][3],
                      stg + baseA[tm] + kqA);
            #pragma unroll
            for (int g = 0; g < 4; g++)
                LDSM4(bh[g][0], bh[g][1], bh[g][2], bh[g][3],
                      stg + baseB[g] + kqB);
            #pragma unroll
            for (int tm = 0; tm < 4; tm++) {
                #pragma unroll
                for (int g = 0; g < 4; g++) {
                    #pragma unroll
                    for (int h = 0; h < 2; h++) {
                        mma16816(acc[tm][g * 2 + h], ah[tm], bh[g][2 * h], bh[g][2 * h + 1]);
                    }
                }
            }
        }
    }

    // ---- epilogue: add bias, store ----
    float2 bv[8];
    #pragma unroll
    for (int j = 0; j < 8; j++) {
        const int n = bn + wn * 64 + j * 8 + 2 * (lane & 3);
        bv[j] = *(const float2*)(bias + n);
    }
    #pragma unroll
    for (int tm = 0; tm < 4; tm++) {
        const int r0 = bm + wm * 64 + tm * 16 + (lane >> 2);
        #pragma unroll
        for (int j = 0; j < 8; j++) {
            const int n = bn + wn * 64 + j * 8 + 2 * (lane & 3);
            float2 o0, o1;
            o0.x = acc[tm][j][0] + bv[j].x;
            o0.y = acc[tm][j][1] + bv[j].y;
            o1.x = acc[tm][j][2] + bv[j].x;
            o1.y = acc[tm][j][3] + bv[j].y;
            *(float2*)(C + (size_t)r0 * NDIM + n)       = o0;
            *(float2*)(C + (size_t)(r0 + 8) * NDIM + n) = o1;
        }
    }
}

// ====================== host launch ======================
extern "C" void kernel_launch(void* const* d_in, const int* in_sizes, int n_in,
                              void* d_out, int out_size) {
    const float* x    = (const float*)d_in[0];   // (4,4096,2048) fp32
    const float* W    = (const float*)d_in[1];   // (2048,2048) fp32
    const float* bias = (const float*)d_in[2];   // (2048,) fp32
    float* out        = (float*)d_out;

    static bool attr_set = false;
    if (!attr_set) {
        cudaFuncSetAttribute(had_gemm_f16, cudaFuncAttributeMaxDynamicSharedMemorySize,
                             SMEM_TOTAL);
        attr_set = true;
    }

    const int conv_blocks = (M_ROWS * KDIM / 8) / 512;   // 8192... (2 float4/thread)
    preprocess<<<D_DIM + (M_ROWS * KDIM / 4 / 512), 256>>>(W, x);
    (void)conv_blocks;

    dim3 grid(NDIM / BN, M_ROWS / BM);   // bn fastest -> A-stripe L2 reuse
    had_gemm_f16<<<grid, 256, SMEM_TOTAL>>>(bias, out);
}

// round 10
// speedup vs baseline: 1.5695x; 1.5695x over previous
#include <cuda_runtime.h>
#include <cuda_fp16.h>
#include <cstdint>

// out[m,o] = sum_d FWHT(x)[m,d] * W[o,d] / sqrt(D) + b[o]
// Hadamard symmetric => FWHT(x) @ W^T == x @ (FWHT_rows(W))^T.
// fp16 single-pass HMMA GEMM w/ fp32 acc.
// R10: exact R8 inner config (16 warps, 64x32 tiles, INLINE swizzle offsets --
// R9 proved hoisting regresses HMMA scheduling) + BK=128 chunks / 2 stages
// to halve the per-chunk barrier+drain overhead (32 -> 16 syncs).

#define D_DIM 2048
#define M_ROWS 16384
#define KDIM 2048
#define NDIM 2048

#define BM 256
#define BN 128
#define BKH 64                       // layout sub-chunk (same as R8 BK)
#define NCH (KDIM / (2 * BKH))       // 16 double-chunks
#define TILE_A_B (BM * 128)          // 32 KB per k-half
#define TILE_B_B (BN * 128)          // 16 KB per k-half
#define HALF_B (TILE_A_B + TILE_B_B) // 48 KB
#define STAGE_B (2 * HALF_B)         // 96 KB (BK=128)
#define SMEM_TOTAL (2 * STAGE_B)     // 192 KB, 1 CTA/SM

// ---- device-global scratch ----
__device__ __half g_W_h[(size_t)NDIM * KDIM];     // 8 MB
__device__ __half g_x_h[(size_t)M_ROWS * KDIM];   // 64 MB

// ====================== PTX helpers ======================
__device__ __forceinline__ uint32_t smem_u32(const void* p) {
    uint32_t a;
    asm("{ .reg .u64 t; cvta.to.shared.u64 t, %1; cvt.u32.u64 %0, t; }" : "=r"(a) : "l"(p));
    return a;
}
#define CP16(dst, src) \
    asm volatile("cp.async.cg.shared.global [%0], [%1], 16;" :: "r"(dst), "l"(src))
#define CP_COMMIT() asm volatile("cp.async.commit_group;" ::: "memory")
#define CP_WAIT0()  asm volatile("cp.async.wait_group 0;" ::: "memory")

#define LDSM4(r0, r1, r2, r3, addr) \
    asm volatile("ldmatrix.sync.aligned.m8n8.x4.shared.b16 {%0,%1,%2,%3}, [%4];" \
                 : "=r"(r0), "=r"(r1), "=r"(r2), "=r"(r3) : "r"(addr))

__device__ __forceinline__ void mma16816(float* c, const uint32_t* a,
                                         uint32_t b0, uint32_t b1) {
    asm volatile(
        "mma.sync.aligned.m16n8k16.row.col.f32.f16.f16.f32 "
        "{%0,%1,%2,%3}, {%4,%5,%6,%7}, {%8,%9}, {%0,%1,%2,%3};"
        : "+f"(c[0]), "+f"(c[1]), "+f"(c[2]), "+f"(c[3])
        : "r"(a[0]), "r"(a[1]), "r"(a[2]), "r"(a[3]), "r"(b0), "r"(b1));
}

// ============ Kernel 1 (merged preprocessing) ============
__global__ __launch_bounds__(256) void preprocess(const float* __restrict__ W,
                                                  const float* __restrict__ x) {
    __shared__ float s[D_DIM];
    const int tid = threadIdx.x;
    if (blockIdx.x < D_DIM) {
        const float* row = W + (size_t)blockIdx.x * D_DIM;
        for (int i = tid; i < D_DIM; i += 256) s[i] = row[i];
        __syncthreads();
        #pragma unroll
        for (int lg = 0; lg < 11; lg++) {
            int h = 1 << lg;
            #pragma unroll
            for (int q = 0; q < (D_DIM / 2) / 256; q++) {
                int p = tid + q * 256;
                int i = ((p >> lg) << (lg + 1)) | (p & (h - 1));
                float a = s[i], c = s[i + h];
                s[i] = a + c;
                s[i + h] = a - c;
            }
            __syncthreads();
        }
        const float scale = 0.02209708691207961f;  // 1/sqrt(2048)
        size_t base = (size_t)blockIdx.x * D_DIM;
        for (int i = tid; i < D_DIM; i += 256)
            g_W_h[base + i] = __float2half_rn(s[i] * scale);
    } else {
        size_t i = (size_t)(blockIdx.x - D_DIM) * 256 + tid;   // float4 index
        float4 v = ((const float4*)x)[i];
        ((__half2*)g_x_h)[2 * i]     = __floats2half2_rn(v.x, v.y);
        ((__half2*)g_x_h)[2 * i + 1] = __floats2half2_rn(v.z, v.w);
    }
}

// ====================== Kernel 2: fp16 HMMA GEMM + bias ======================
// 16 warps: wm = wid&3 (4 x 64 rows), wn = wid>>2 (4 x 32 cols).
// Warp tile 64x32: per k16-step A 4 LDSM4 + B 2 LDSM4, 16 MMAs.
// Inline swizzled offsets (R8-proven scheduling).

__global__ __launch_bounds__(512, 1)
void had_gemm_f16(const float* __restrict__ bias, float* __restrict__ C) {
    extern __shared__ __align__(1024) char smem[];
    const uint32_t sm0 = smem_u32(smem);

    const int tid  = threadIdx.x;
    const int lane = tid & 31;
    const int wid  = tid >> 5;
    const int wm   = wid & 3;
    const int wn   = wid >> 2;

    const int bm = blockIdx.y * BM;
    const int bn = blockIdx.x * BN;

    // ---- cp.async loader mapping: 512 threads, row lr (+64*i), chunk lc ----
    const int lr = tid >> 3;      // 0..63
    const int lc = tid & 7;       // 16B chunk
    const uint32_t swchunk = (uint32_t)((lc ^ (lr & 7)) << 4);

    const __half* srcA = g_x_h + (size_t)(bm + lr) * KDIM + lc * 8;
    const __half* srcB = g_W_h + (size_t)(bn + lr) * KDIM + lc * 8;

    float acc[4][4][4];
    #pragma unroll
    for (int i = 0; i < 4; i++)
        #pragma unroll
        for (int j = 0; j < 4; j++)
            #pragma unroll
            for (int q = 0; q < 4; q++) acc[i][j][q] = 0.f;

    // ---- ldmatrix per-thread address components (inline recompute) ----
    const int raBase = wm * 64 + (lane & 15);                      // + tm*16
    const int cA     = lane >> 4;
    const int rbBase = wn * 32 + (lane & 7) + ((lane >> 4) << 3);  // + g*16
    const int cB     = (lane >> 3) & 1;

    // issue a full BK=128 chunk (two k-halves) into stage s
    auto issue = [&](int s, int t) {
        const uint32_t sb = sm0 + s * STAGE_B;
        #pragma unroll
        for (int half = 0; half < 2; half++) {
            const uint32_t hb = sb + half * HALF_B;
            const size_t ko = (size_t)t * (2 * BKH) + half * BKH;
            #pragma unroll
            for (int i = 0; i < 4; i++) {             // A: 256 rows / 64
                uint32_t roff = (uint32_t)(lr + 64 * i) * 128 + swchunk;
                CP16(hb + roff, srcA + ko + (size_t)(64 * i) * KDIM);
            }
            #pragma unroll
            for (int i = 0; i < 2; i++) {             // B: 128 rows / 64
                uint32_t roff = (uint32_t)(lr + 64 * i) * 128 + swchunk;
                CP16(hb + TILE_A_B + roff, srcB + ko + (size_t)(64 * i) * KDIM);
            }
        }
    };

    // 2-stage pipeline: copy of chunk t+1 overlaps compute of chunk t.
    // Stage written at iter t is (t+1)&1; stage read is t&1 -> disjoint.
    // The sync below issue-barrier also orders last iter's reads of stage
    // (t+1)&1 (== chunk t-1) before its overwrite.
    issue(0, 0); CP_COMMIT();

    for (int t = 0; t < NCH; t++) {
        CP_WAIT0();            // chunk t fully in smem
        __syncthreads();

        if (t + 1 < NCH) { issue((t + 1) & 1, t + 1); CP_COMMIT(); }

        const uint32_t sb = sm0 + (t & 1) * STAGE_B;

        #pragma unroll
        for (int half = 0; half < 2; half++) {
            const uint32_t aT = sb + half * HALF_B;
            const uint32_t bT = aT + TILE_A_B;
            #pragma unroll
            for (int ks = 0; ks < 4; ks++) {
                uint32_t ah[4][4], bh[2][4];
                #pragma unroll
                for (int tm = 0; tm < 4; tm++) {
                    const int r = raBase + tm * 16;
                    const uint32_t off = (uint32_t)r * 128 +
                                         (uint32_t)(((2 * ks + cA) ^ (r & 7)) << 4);
                    LDSM4(ah[tm][0], ah[tm][1], ah[tm][2], ah[tm][3], aT + off);
                }
                #pragma unroll
                for (int g = 0; g < 2; g++) {
                    const int r = rbBase + g * 16;
                    const uint32_t off = (uint32_t)r * 128 +
                                         (uint32_t)(((2 * ks + cB) ^ (r & 7)) << 4);
                    LDSM4(bh[g][0], bh[g][1], bh[g][2], bh[g][3], bT + off);
                }
                #pragma unroll
                for (int tm = 0; tm < 4; tm++) {
                    #pragma unroll
                    for (int g = 0; g < 2; g++) {
                        #pragma unroll
                        for (int h = 0; h < 2; h++) {
                            mma16816(acc[tm][g * 2 + h], ah[tm],
                                     bh[g][2 * h], bh[g][2 * h + 1]);
                        }
                    }
                }
            }
        }
    }

    // ---- epilogue: add bias, store ----
    float2 bv[4];
    #pragma unroll
    for (int j = 0; j < 4; j++) {
        const int n = bn + wn * 32 + j * 8 + 2 * (lane & 3);
        bv[j] = *(const float2*)(bias + n);
    }
    #pragma unroll
    for (int tm = 0; tm < 4; tm++) {
        const int r0 = bm + wm * 64 + tm * 16 + (lane >> 2);
        #pragma unroll
        for (int j = 0; j < 4; j++) {
            const int n = bn + wn * 32 + j * 8 + 2 * (lane & 3);
            float2 o0, o1;
            o0.x = acc[tm][j][0] + bv[j].x;
            o0.y = acc[tm][j][1] + bv[j].y;
            o1.x = acc[tm][j][2] + bv[j].x;
            o1.y = acc[tm][j][3] + bv[j].y;
            *(float2*)(C + (size_t)r0 * NDIM + n)       = o0;
            *(float2*)(C + (size_t)(r0 + 8) * NDIM + n) = o1;
        }
    }
}

// ====================== host launch ======================
extern "C" void kernel_launch(void* const* d_in, const int* in_sizes, int n_in,
                              void* d_out, int out_size) {
    const float* x    = (const float*)d_in[0];   // (4,4096,2048) fp32
    const float* W    = (const float*)d_in[1];   // (2048,2048) fp32
    const float* bias = (const float*)d_in[2];   // (2048,) fp32
    float* out        = (float*)d_out;

    static bool attr_set = false;
    if (!attr_set) {
        cudaFuncSetAttribute(had_gemm_f16, cudaFuncAttributeMaxDynamicSharedMemorySize,
                             SMEM_TOTAL);
        attr_set = true;
    }

    const int conv_blocks = (M_ROWS * KDIM / 4) / 256;   // 32768
    preprocess<<<D_DIM + conv_blocks, 256>>>(W, x);

    dim3 grid(NDIM / BN, M_ROWS / BM);   // bn fastest -> A-stripe L2 reuse
    had_gemm_f16<<<grid, 512, SMEM_TOTAL>>>(bias, out);
}

// round 11
// speedup vs baseline: 1.7178x; 1.0945x over previous
#include <cuda_runtime.h>
#include <cuda_fp16.h>
#include <cstdint>

// out[m,o] = sum_d FWHT(x)[m,d] * W[o,d] / sqrt(D) + b[o]
// Hadamard symmetric => FWHT(x) @ W^T == x @ (FWHT_rows(W))^T.
// fp16 single-pass HMMA GEMM w/ fp32 acc.
// R11 = R10 + (a) next-chunk copy issued between k-halves to de-collide the
// post-barrier LDSM burst, (b) FWHT does 2 W-rows per block (shared syncs),
// (c) x-converter does 2 float4/thread.

#define D_DIM 2048
#define M_ROWS 16384
#define KDIM 2048
#define NDIM 2048

#define BM 256
#define BN 128
#define BKH 64                       // layout sub-chunk
#define NCH (KDIM / (2 * BKH))       // 16 double-chunks
#define TILE_A_B (BM * 128)          // 32 KB per k-half
#define TILE_B_B (BN * 128)          // 16 KB per k-half
#define HALF_B (TILE_A_B + TILE_B_B) // 48 KB
#define STAGE_B (2 * HALF_B)         // 96 KB (BK=128)
#define SMEM_TOTAL (2 * STAGE_B)     // 192 KB, 1 CTA/SM

// ---- device-global scratch ----
__device__ __half g_W_h[(size_t)NDIM * KDIM];     // 8 MB
__device__ __half g_x_h[(size_t)M_ROWS * KDIM];   // 64 MB

// ====================== PTX helpers ======================
__device__ __forceinline__ uint32_t smem_u32(const void* p) {
    uint32_t a;
    asm("{ .reg .u64 t; cvta.to.shared.u64 t, %1; cvt.u32.u64 %0, t; }" : "=r"(a) : "l"(p));
    return a;
}
#define CP16(dst, src) \
    asm volatile("cp.async.cg.shared.global [%0], [%1], 16;" :: "r"(dst), "l"(src))
#define CP_COMMIT() asm volatile("cp.async.commit_group;" ::: "memory")
#define CP_WAIT0()  asm volatile("cp.async.wait_group 0;" ::: "memory")

#define LDSM4(r0, r1, r2, r3, addr) \
    asm volatile("ldmatrix.sync.aligned.m8n8.x4.shared.b16 {%0,%1,%2,%3}, [%4];" \
                 : "=r"(r0), "=r"(r1), "=r"(r2), "=r"(r3) : "r"(addr))

__device__ __forceinline__ void mma16816(float* c, const uint32_t* a,
                                         uint32_t b0, uint32_t b1) {
    asm volatile(
        "mma.sync.aligned.m16n8k16.row.col.f32.f16.f16.f32 "
        "{%0,%1,%2,%3}, {%4,%5,%6,%7}, {%8,%9}, {%0,%1,%2,%3};"
        : "+f"(c[0]), "+f"(c[1]), "+f"(c[2]), "+f"(c[3])
        : "r"(a[0]), "r"(a[1]), "r"(a[2]), "r"(a[3]), "r"(b0), "r"(b1));
}

// ============ Kernel 1 (merged preprocessing) ============
// blocks [0, 1024):  FWHT two rows of W -> fp16 (shared syncs)
// blocks [1024, ..): convert 2 float4-chunks of x -> fp16
#define FWHT_BLKS (D_DIM / 2)
__global__ __launch_bounds__(256) void preprocess(const float* __restrict__ W,
                                                  const float* __restrict__ x) {
    __shared__ float s[2 * D_DIM];
    const int tid = threadIdx.x;
    if (blockIdx.x < FWHT_BLKS) {
        const float* rows = W + (size_t)blockIdx.x * 2 * D_DIM;
        for (int i = tid; i < 2 * D_DIM; i += 256) s[i] = rows[i];
        __syncthreads();
        #pragma unroll
        for (int lg = 0; lg < 11; lg++) {
            int h = 1 << lg;
            #pragma unroll
            for (int rr = 0; rr < 2; rr++) {
                float* sr = s + rr * D_DIM;
                #pragma unroll
                for (int q = 0; q < (D_DIM / 2) / 256; q++) {
                    int p = tid + q * 256;
                    int i = ((p >> lg) << (lg + 1)) | (p & (h - 1));
                    float a = sr[i], c = sr[i + h];
                    sr[i] = a + c;
                    sr[i + h] = a - c;
                }
            }
            __syncthreads();
        }
        const float scale = 0.02209708691207961f;  // 1/sqrt(2048)
        size_t base = (size_t)blockIdx.x * 2 * D_DIM;
        for (int i = tid; i < 2 * D_DIM; i += 256)
            g_W_h[base + i] = __float2half_rn(s[i] * scale);
    } else {
        size_t b = (size_t)(blockIdx.x - FWHT_BLKS) * 512 + tid;   // float4 idx
        #pragma unroll
        for (int u = 0; u < 2; u++) {
            size_t i = b + (size_t)u * 256;
            float4 v = ((const float4*)x)[i];
            ((__half2*)g_x_h)[2 * i]     = __floats2half2_rn(v.x, v.y);
            ((__half2*)g_x_h)[2 * i + 1] = __floats2half2_rn(v.z, v.w);
        }
    }
}

// ====================== Kernel 2: fp16 HMMA GEMM + bias ======================
// 16 warps: wm = wid&3 (4 x 64 rows), wn = wid>>2 (4 x 32 cols).
// Warp tile 64x32: per k16-step A 4 LDSM4 + B 2 LDSM4, 16 MMAs.
// Next-chunk cp.async issued between k-halves (away from post-barrier burst).

__global__ __launch_bounds__(512, 1)
void had_gemm_f16(const float* __restrict__ bias, float* __restrict__ C) {
    extern __shared__ __align__(1024) char smem[];
    const uint32_t sm0 = smem_u32(smem);

    const int tid  = threadIdx.x;
    const int lane = tid & 31;
    const int wid  = tid >> 5;
    const int wm   = wid & 3;
    const int wn   = wid >> 2;

    const int bm = blockIdx.y * BM;
    const int bn = blockIdx.x * BN;

    // ---- cp.async loader mapping: 512 threads, row lr (+64*i), chunk lc ----
    const int lr = tid >> 3;      // 0..63
    const int lc = tid & 7;       // 16B chunk
    const uint32_t swchunk = (uint32_t)((lc ^ (lr & 7)) << 4);

    const __half* srcA = g_x_h + (size_t)(bm + lr) * KDIM + lc * 8;
    const __half* srcB = g_W_h + (size_t)(bn + lr) * KDIM + lc * 8;

    float acc[4][4][4];
    #pragma unroll
    for (int i = 0; i < 4; i++)
        #pragma unroll
        for (int j = 0; j < 4; j++)
            #pragma unroll
            for (int q = 0; q < 4; q++) acc[i][j][q] = 0.f;

    // ---- ldmatrix per-thread address components (inline recompute) ----
    const int raBase = wm * 64 + (lane & 15);                      // + tm*16
    const int cA     = lane >> 4;
    const int rbBase = wn * 32 + (lane & 7) + ((lane >> 4) << 3);  // + g*16
    const int cB     = (lane >> 3) & 1;

    // issue ONE k-half (BKH=64) of chunk t into stage s, half index h01
    auto issue_half = [&](int s, int t, int h01) {
        const uint32_t hb = sm0 + s * STAGE_B + h01 * HALF_B;
        const size_t ko = (size_t)t * (2 * BKH) + (size_t)h01 * BKH;
        #pragma unroll
        for (int i = 0; i < 4; i++) {             // A: 256 rows / 64
            uint32_t roff = (uint32_t)(lr + 64 * i) * 128 + swchunk;
            CP16(hb + roff, srcA + ko + (size_t)(64 * i) * KDIM);
        }
        #pragma unroll
        for (int i = 0; i < 2; i++) {             // B: 128 rows / 64
            uint32_t roff = (uint32_t)(lr + 64 * i) * 128 + swchunk;
            CP16(hb + TILE_A_B + roff, srcB + ko + (size_t)(64 * i) * KDIM);
        }
    };

    // compute one k-half currently in smem
    auto compute_half = [&](uint32_t aT) {
        const uint32_t bT = aT + TILE_A_B;
        #pragma unroll
        for (int ks = 0; ks < 4; ks++) {
            uint32_t ah[4][4], bh[2][4];
            #pragma unroll
            for (int tm = 0; tm < 4; tm++) {
                const int r = raBase + tm * 16;
                const uint32_t off = (uint32_t)r * 128 +
                                     (uint32_t)(((2 * ks + cA) ^ (r & 7)) << 4);
                LDSM4(ah[tm][0], ah[tm][1], ah[tm][2], ah[tm][3], aT + off);
            }
            #pragma unroll
            for (int g = 0; g < 2; g++) {
                const int r = rbBase + g * 16;
                const uint32_t off = (uint32_t)r * 128 +
                                     (uint32_t)(((2 * ks + cB) ^ (r & 7)) << 4);
                LDSM4(bh[g][0], bh[g][1], bh[g][2], bh[g][3], bT + off);
            }
            #pragma unroll
            for (int tm = 0; tm < 4; tm++) {
                #pragma unroll
                for (int g = 0; g < 2; g++) {
                    #pragma unroll
                    for (int h = 0; h < 2; h++) {
                        mma16816(acc[tm][g * 2 + h], ah[tm],
                                 bh[g][2 * h], bh[g][2 * h + 1]);
                    }
                }
            }
        }
    };

    // 2-stage pipeline; write stage (t+1)&1 != read stage t&1. The top-of-loop
    // barrier orders all prior reads of the write-stage before overwrite.
    issue_half(0, 0, 0); issue_half(0, 0, 1); CP_COMMIT();

    for (int t = 0; t < NCH; t++) {
        CP_WAIT0();            // chunk t fully in smem
        __syncthreads();

        const uint32_t sb = sm0 + (t & 1) * STAGE_B;

        // half 0 compute first (post-barrier LDSM burst runs alone on LSU)
        compute_half(sb);

        // now issue next chunk's copies (LSU quiet zone)
        if (t + 1 < NCH) {
            issue_half((t + 1) & 1, t + 1, 0);
            issue_half((t + 1) & 1, t + 1, 1);
        }
        CP_COMMIT();

        // half 1 compute
        compute_half(sb + HALF_B);
    }

    // ---- epilogue: add bias, store ----
    float2 bv[4];
    #pragma unroll
    for (int j = 0; j < 4; j++) {
        const int n = bn + wn * 32 + j * 8 + 2 * (lane & 3);
        bv[j] = *(const float2*)(bias + n);
    }
    #pragma unroll
    for (int tm = 0; tm < 4; tm++) {
        const int r0 = bm + wm * 64 + tm * 16 + (lane >> 2);
        #pragma unroll
        for (int j = 0; j < 4; j++) {
            const int n = bn + wn * 32 + j * 8 + 2 * (lane & 3);
            float2 o0, o1;
            o0.x = acc[tm][j][0] + bv[j].x;
            o0.y = acc[tm][j][1] + bv[j].y;
            o1.x = acc[tm][j][2] + bv[j].x;
            o1.y = acc[tm][j][3] + bv[j].y;
            *(float2*)(C + (size_t)r0 * NDIM + n)       = o0;
            *(float2*)(C + (size_t)(r0 + 8) * NDIM + n) = o1;
        }
    }
}

// ====================== host launch ======================
extern "C" void kernel_launch(void* const* d_in, const int* in_sizes, int n_in,
                              void* d_out, int out_size) {
    const float* x    = (const float*)d_in[0];   // (4,4096,2048) fp32
    const float* W    = (const float*)d_in[1];   // (2048,2048) fp32
    const float* bias = (const float*)d_in[2];   // (2048,) fp32
    float* out        = (float*)d_out;

    static bool attr_set = false;
    if (!attr_set) {
        cudaFuncSetAttribute(had_gemm_f16, cudaFuncAttributeMaxDynamicSharedMemorySize,
                             SMEM_TOTAL);
        attr_set = true;
    }

    const int conv_blocks = (M_ROWS * KDIM / 4) / 512;   // 16384 (2 float4/thr)
    preprocess<<<FWHT_BLKS + conv_blocks, 256>>>(W, x);

    dim3 grid(NDIM / BN, M_ROWS / BM);   // bn fastest -> A-stripe L2 reuse
    had_gemm_f16<<<grid, 512, SMEM_TOTAL>>>(bias, out);
}